// round 16
// baseline (speedup 1.0000x reference)
#include <cuda_runtime.h>
#include <math.h>

#define NSAMP   4194304
#define HOP     128
#define NFFT    512
#define NFRAMES 32769
#define NBINS   257
#define OUT_STRIDE (3*NBINS)
#define WPB     8            // warps (=frames) per block
#define RBLOCKS 512          // reducer blocks (all in wave 1)

// Scratch (no cudaMalloc allowed)
__device__ float2   g_partial[RBLOCKS];
__device__ unsigned g_ctr  = 0;   // self-resetting via atomicInc wrap
__device__ unsigned g_flag = 0;   // stays 1 after first call; c identical per call
__device__ float    g_c;

// ---- packed f32x2 helpers (Blackwell FADD2/FMUL2/FFMA2) ------------------
__device__ __forceinline__ float2 f2add(float2 a, float2 b) {
    float2 r;
    asm("{\n\t.reg .b64 ra, rb, rc;\n\t"
        "mov.b64 ra, {%2,%3};\n\t"
        "mov.b64 rb, {%4,%5};\n\t"
        "add.rn.f32x2 rc, ra, rb;\n\t"
        "mov.b64 {%0,%1}, rc;\n\t}"
        : "=f"(r.x), "=f"(r.y)
        : "f"(a.x), "f"(a.y), "f"(b.x), "f"(b.y));
    return r;
}
// (s*x.x + y.x, s*x.y + y.y)
__device__ __forceinline__ float2 f2fma(float s, float2 x, float2 y) {
    float2 r;
    asm("{\n\t.reg .b64 rs, rx, ry, rr;\n\t"
        "mov.b64 rs, {%2,%2};\n\t"
        "mov.b64 rx, {%3,%4};\n\t"
        "mov.b64 ry, {%5,%6};\n\t"
        "fma.rn.f32x2 rr, rs, rx, ry;\n\t"
        "mov.b64 {%0,%1}, rr;\n\t}"
        : "=f"(r.x), "=f"(r.y)
        : "f"(s), "f"(x.x), "f"(x.y), "f"(y.x), "f"(y.y));
    return r;
}
// (s*x.x, s*x.y)
__device__ __forceinline__ float2 f2mul(float s, float2 x) {
    float2 r;
    asm("{\n\t.reg .b64 rs, rx, rr;\n\t"
        "mov.b64 rs, {%2,%2};\n\t"
        "mov.b64 rx, {%3,%4};\n\t"
        "mul.rn.f32x2 rr, rs, rx;\n\t"
        "mov.b64 {%0,%1}, rr;\n\t}"
        : "=f"(r.x), "=f"(r.y)
        : "f"(s), "f"(x.x), "f"(x.y));
    return r;
}

// packed complex multiply: a*b via splat(a.x)*b + splat(a.y)*(-b.y, b.x)
// cmul2((1,0), r) == r exactly.
__device__ __forceinline__ float2 cmul2(float2 a, float2 b) {
    float2 m = f2mul(a.x, b);
    return f2fma(a.y, make_float2(-b.y, b.x), m);
}

__device__ __forceinline__ float2 cadd(float2 a, float2 b) { return f2add(a, b); }
__device__ __forceinline__ float2 csub(float2 a, float2 b) { return f2fma(-1.f, b, a); }  // exact a-b
__device__ __forceinline__ float2 mul_mi(float2 z) { return make_float2(z.y, -z.x); }  // -i*z

// Branchless feature triple from (re, im)
__device__ __forceinline__ void features(float re, float im,
                                         float& lm, float& sv, float& cv) {
    float r2 = fmaxf(re * re + im * im, 1e-45f);
    float inv = rsqrtf(r2);
    lm = __logf(fmaf(r2, inv, 1e-9f));
    sv = im * inv;
    cv = re * inv;
}

// ---------------------------------------------------------------------------
// Fused kernel (R14 structure): inline reduction (blocks < RBLOCKS) +
// one warp = one frame register FFT. Packed f32x2 for complex add/sub,
// butterfly combines, complex multiplies, and the epilogue unpack.
// ---------------------------------------------------------------------------
__global__ __launch_bounds__(256, 5) void stft_fused(const float* __restrict__ audio,
                                                     float* __restrict__ out) {
    __shared__ float2 s_win[256];           // (hann[2n], hann[2n+1])
    __shared__ float  s_feat[WPB][3][288];  // per-warp transpose staging (stride 9)
    __shared__ float  s_r1[8], s_r2[8];
    __shared__ double s_d1[8], s_d2[8];

    const int tid  = threadIdx.x;
    const int warp = tid >> 5;
    const int p    = tid & 31;
    const unsigned FULL = 0xffffffffu;

    {
        float c0 = cospif((float)(2 * tid)     * (1.f / 256.f));
        float c1 = cospif((float)(2 * tid + 1) * (1.f / 256.f));
        s_win[tid] = make_float2(0.5f * (1.f - c0), 0.5f * (1.f - c1));
    }
    __syncthreads();

    // ---------------- phase A: inline reduction (first RBLOCKS blocks) ---
    if (blockIdx.x < RBLOCKS) {
        const float4* x4 = (const float4*)audio;
        const int gt = blockIdx.x * 256 + tid;          // 0..131071
        float sum = 0.f, sq = 0.f;
        #pragma unroll
        for (int k = 0; k < 8; ++k) {
            float4 v = x4[gt + k * 131072];
            sum += (v.x + v.y) + (v.z + v.w);
            sq  += (v.x*v.x + v.y*v.y) + (v.z*v.z + v.w*v.w);
        }
        #pragma unroll
        for (int o = 16; o > 0; o >>= 1) {
            sum += __shfl_xor_sync(FULL, sum, o);
            sq  += __shfl_xor_sync(FULL, sq,  o);
        }
        if (p == 0) { s_r1[warp] = sum; s_r2[warp] = sq; }
        __syncthreads();
        __shared__ bool is_last;
        if (tid == 0) {
            float a = 0.f, b = 0.f;
            #pragma unroll
            for (int w = 0; w < 8; ++w) { a += s_r1[w]; b += s_r2[w]; }
            g_partial[blockIdx.x] = make_float2(a, b);
            __threadfence();
            is_last = (atomicInc(&g_ctr, RBLOCKS - 1) == RBLOCKS - 1);
        }
        __syncthreads();
        if (is_last) {
            double ds = 0.0, dq = 0.0;
            #pragma unroll
            for (int k = 0; k < 2; ++k) {
                float2 pp = g_partial[tid + 256 * k];
                ds += (double)pp.x; dq += (double)pp.y;
            }
            #pragma unroll
            for (int o = 16; o > 0; o >>= 1) {
                ds += __shfl_xor_sync(FULL, ds, o);
                dq += __shfl_xor_sync(FULL, dq, o);
            }
            if (p == 0) { s_d1[warp] = ds; s_d2[warp] = dq; }
            __syncthreads();
            if (tid == 0) {
                double S = 0.0, SS = 0.0;
                #pragma unroll
                for (int w = 0; w < 8; ++w) { S += s_d1[w]; SS += s_d2[w]; }
                double mean = S / (double)NSAMP;
                double var  = (SS - S * S / (double)NSAMP) / (double)(NSAMP - 1);
                g_c = (float)(mean / sqrt(var));
                __threadfence();
                atomicExch(&g_flag, 1u);
            }
        }
    }

    // ---------------- phase B: per-warp frame FFT -----------------------
    const int frame = blockIdx.x * WPB + warp;
    if (frame >= NFRAMES) return;

    const int base = frame * HOP - NFFT / 2;

    // load + reflect + window + pack (NO -c: folded into bins 0,1 later)
    float2 C[8];
    if (base >= 0 && base + NFFT <= NSAMP) {       // uniform per-warp branch
        #pragma unroll
        for (int q = 0; q < 8; ++q) {
            int n = 32 * q + p;
            float2 v = *(const float2*)(audio + base + 2 * n);
            float2 h = s_win[n];                   // lane-contiguous: conflict-free
            C[q] = make_float2(v.x * h.x, v.y * h.y);
        }
    } else {                                       // frames 0,1,32767,32768 only
        #pragma unroll
        for (int q = 0; q < 8; ++q) {
            int n = 32 * q + p;
            int p0 = base + 2 * n, p1 = p0 + 1;
            if (p0 < 0) p0 = -p0; else if (p0 >= NSAMP) p0 = 2 * NSAMP - 2 - p0;
            if (p1 < 0) p1 = -p1; else if (p1 >= NSAMP) p1 = 2 * NSAMP - 2 - p1;
            float2 h = s_win[n];
            C[q] = make_float2(audio[p0] * h.x, audio[p1] * h.y);
        }
    }

    // step 1: in-register 8-pt DFT over q (adds/subs + const cmuls packed)
    float2 A[8];
    {
        const float RC = 0.70710678118654752440f;
        float2 t0 = cadd(C[0], C[4]);
        float2 t1 = csub(C[0], C[4]);
        float2 t2 = cadd(C[2], C[6]);
        float2 t3 = csub(C[2], C[6]);
        float2 E0 = cadd(t0, t2);
        float2 E2 = csub(t0, t2);
        float2 t3m = mul_mi(t3);
        float2 E1 = cadd(t1, t3m);
        float2 E3 = csub(t1, t3m);
        float2 u0 = cadd(C[1], C[5]);
        float2 u1 = csub(C[1], C[5]);
        float2 u2 = cadd(C[3], C[7]);
        float2 u3 = csub(C[3], C[7]);
        float2 O0 = cadd(u0, u2);
        float2 O2 = csub(u0, u2);
        float2 u3m = mul_mi(u3);
        float2 O1 = cadd(u1, u3m);
        float2 O3 = csub(u1, u3m);
        float2 w1O1 = cmul2(make_float2(RC, -RC), O1);
        float2 w2O2 = mul_mi(O2);
        float2 w3O3 = cmul2(make_float2(-RC, -RC), O3);
        A[0] = cadd(E0, O0);   A[4] = csub(E0, O0);
        A[1] = cadd(E1, w1O1); A[5] = csub(E1, w1O1);
        A[2] = cadd(E2, w2O2); A[6] = csub(E2, w2O2);
        A[3] = cadd(E3, w3O3); A[7] = csub(E3, w3O3);
    }

    // step 2: twiddle by e^{-2pi i p s/256} = w1^s (log-depth tree, packed)
    {
        float sn, cs;
        sincospif((float)p * (1.f / 128.f), &sn, &cs);
        float2 w1 = make_float2(cs, -sn);
        float2 w2 = cmul2(w1, w1);
        float2 w3 = cmul2(w2, w1);
        float2 w4 = cmul2(w2, w2);
        float2 w5 = cmul2(w4, w1);
        float2 w6 = cmul2(w3, w3);
        float2 w7 = cmul2(w4, w3);
        C[0] = A[0];
        C[1] = cmul2(A[1], w1);
        C[2] = cmul2(A[2], w2);
        C[3] = cmul2(A[3], w3);
        C[4] = cmul2(A[4], w4);
        C[5] = cmul2(A[5], w5);
        C[6] = cmul2(A[6], w6);
        C[7] = cmul2(A[7], w7);
    }

    // step 3: 32-pt DIF across lanes (fully packed)
    {
        float sn, cs;
        sincospif((float)(p & 15) * (1.f / 16.f), &sn, &cs);
        float2 w = make_float2(cs, -sn);       // e^{-i*pi*(p&15)/16}, m=16
        #pragma unroll
        for (int st = 0; st < 3; ++st) {
            const int m = 16 >> st;            // 16, 8, 4
            const bool up = (p & m) != 0;
            const float sgn = up ? -1.f : 1.f;
            const float2 we = up ? w : make_float2(1.f, 0.f);
            #pragma unroll
            for (int s = 0; s < 8; ++s) {
                float2 x = C[s];
                float2 y;
                y.x = __shfl_xor_sync(FULL, x.x, m);
                y.y = __shfl_xor_sync(FULL, x.y, m);
                C[s] = cmul2(we, f2fma(sgn, x, y));  // we=(1,0) exact identity
            }
            if (st < 2) {
                float2 w2 = cmul2(w, w);       // w_{m/2} = (-1)^b w_m^2
                if (p & (m >> 1)) { w2.x = -w2.x; w2.y = -w2.y; }
                w = w2;
            }
        }
        // stage m = 2: rotate by -i only on lanes with (p&3)==3 (exact)
        {
            const bool rot = (p & 3) == 3;
            const float sgn = (p & 2) ? -1.f : 1.f;
            #pragma unroll
            for (int s = 0; s < 8; ++s) {
                float2 x = C[s];
                float2 y;
                y.x = __shfl_xor_sync(FULL, x.x, 2);
                y.y = __shfl_xor_sync(FULL, x.y, 2);
                float2 r = f2fma(sgn, x, y);
                C[s] = rot ? mul_mi(r) : r;
            }
        }
        // stage m = 1: twiddle-free butterfly
        {
            const float sgn = (p & 1) ? -1.f : 1.f;
            #pragma unroll
            for (int s = 0; s < 8; ++s) {
                float2 x = C[s];
                float2 y;
                y.x = __shfl_xor_sync(FULL, x.x, 1);
                y.y = __shfl_xor_sync(FULL, x.y, 1);
                C[s] = f2fma(sgn, x, y);
            }
        }
    }
    const int t = __brev(p) >> 27;             // lane p holds Z[s + 8t]

    // ---------------- acquire c (flag long since set) -------------------
    float cbr = 0.f;
    if (p == 0) {
        while (atomicAdd(&g_flag, 0u) == 0u) {}
        __threadfence();
        cbr = *(volatile float*)&g_c;
    }
    cbr = __shfl_sync(FULL, cbr, 0);

    // ---------------- epilogue: real unpack + features (packed) ---------
    float2 wt;
    {
        float sn, cs;
        sincospif((float)t * (1.f / 32.f), &sn, &cs);
        wt = make_float2(cs, -sn);
    }
    const float WS_C[8] = {1.f, 0.999924702f, 0.999698819f, 0.999322385f,
                           0.998795456f, 0.998118113f, 0.997290457f, 0.996312612f};
    const float WS_S[8] = {0.f, 0.012271538f, 0.024541229f, 0.036807223f,
                           0.049067674f, 0.061320736f, 0.073564564f, 0.085797312f};

    float* fr0 = s_feat[warp][0];
    float* fr1 = s_feat[warp][1];
    float* fr2 = s_feat[warp][2];
    const int psrc0 = __brev((32 - t) & 31) >> 27;

    #pragma unroll
    for (int s = 0; s < 8; ++s) {
        float2 zc;
        if (s == 0) {
            zc.x = __shfl_sync(FULL, C[0].x, psrc0);      // Z[(256-8t)%256]
            zc.y = __shfl_sync(FULL, C[0].y, psrc0);
        } else {
            zc.x = __shfl_xor_sync(FULL, C[8 - s].x, 31); // Z[(8-s)+8(31-t)]
            zc.y = __shfl_xor_sync(FULL, C[8 - s].y, 31);
        }
        float2 zk = C[s];
        // sum = 0.5(zk+zc) = (xer, xox); dif = 0.5(zk-zc) = (-xoy, xei)
        float2 sum = f2mul(0.5f, f2add(zk, zc));
        float2 dif = f2mul(0.5f, f2fma(-1.f, zc, zk));
        float2 E  = make_float2(sum.x, dif.y);   // (xer, xei)
        float2 D  = make_float2(sum.y, -dif.x);  // (xox, xoy)
        float2 Dm = make_float2(dif.x, sum.y);   // (-xoy, xox)
        float2 w = cmul2(make_float2(WS_C[s], -WS_S[s]), wt);
        float2 ri = f2fma(w.y, Dm, f2fma(w.x, D, E));
        float re = ri.x, im = ri.y;
        // c-correction via DFT linearity: H[0]=256, H[1]=-128 (exact)
        if (p == 0) {
            if (s == 0) re -= 256.f * cbr;
            else if (s == 1) re += 128.f * cbr;
        }
        float lm, sv, cv;
        features(re, im, lm, sv, cv);
        int idx = 9 * t + s;                   // conflict-free (9 coprime 32)
        fr0[idx] = lm; fr1[idx] = sv; fr2[idx] = cv;
    }

    float* orow = out + (size_t)frame * OUT_STRIDE;
    if (p == 0) {
        // bin 256: X = Re(Z0) - Im(Z0); H[256]=0 -> no c-correction
        float2 z0 = C[0];
        float re = z0.x - z0.y;
        float lm, sv, cv;
        features(re, 0.f, lm, sv, cv);
        sv = 0.f;
        orow[256] = lm; orow[NBINS + 256] = sv; orow[2 * NBINS + 256] = cv;
    }
    __syncwarp();

    // coalesced copy shared -> gmem
    #pragma unroll
    for (int f = 0; f < 3; ++f) {
        const float* src = s_feat[warp][f];
        #pragma unroll
        for (int cb = 0; cb < 8; ++cb) {
            int k = cb * 32 + p;
            orow[f * NBINS + k] = src[9 * (k >> 3) + (k & 7)];
        }
    }
}

// ---------------------------------------------------------------------------
extern "C" void kernel_launch(void* const* d_in, const int* in_sizes, int n_in,
                              void* d_out, int out_size) {
    const float* audio = (const float*)d_in[0];
    float* out = (float*)d_out;
    stft_fused<<<(NFRAMES + WPB - 1) / WPB, 256>>>(audio, out);
}

// round 17
// speedup vs baseline: 1.0435x; 1.0435x over previous
#include <cuda_runtime.h>
#include <math.h>

#define NSAMP   4194304
#define HOP     128
#define NFFT    512
#define NFRAMES 32769
#define NBINS   257
#define OUT_STRIDE (3*NBINS)
#define WPB     8            // warps (=frames) per block
#define RBLOCKS 512          // reducer blocks (all in wave 1)

// Scratch (no cudaMalloc allowed)
__device__ float2   g_partial[RBLOCKS];
__device__ unsigned g_ctr  = 0;   // self-resetting via atomicInc wrap
__device__ unsigned g_flag = 0;   // stays 1 after first call; c identical per call
__device__ float    g_c;

// ---- packed f32x2 helpers (Blackwell FADD2/FFMA2; bit-exact per lane) ----
__device__ __forceinline__ float2 f2add(float2 a, float2 b) {
    float2 r;
    asm("{\n\t.reg .b64 ra, rb, rc;\n\t"
        "mov.b64 ra, {%2,%3};\n\t"
        "mov.b64 rb, {%4,%5};\n\t"
        "add.rn.f32x2 rc, ra, rb;\n\t"
        "mov.b64 {%0,%1}, rc;\n\t}"
        : "=f"(r.x), "=f"(r.y)
        : "f"(a.x), "f"(a.y), "f"(b.x), "f"(b.y));
    return r;
}
// (s*x.x + y.x, s*x.y + y.y)
__device__ __forceinline__ float2 f2fma(float s, float2 x, float2 y) {
    float2 r;
    asm("{\n\t.reg .b64 rs, rx, ry, rr;\n\t"
        "mov.b64 rs, {%2,%2};\n\t"
        "mov.b64 rx, {%3,%4};\n\t"
        "mov.b64 ry, {%5,%6};\n\t"
        "fma.rn.f32x2 rr, rs, rx, ry;\n\t"
        "mov.b64 {%0,%1}, rr;\n\t}"
        : "=f"(r.x), "=f"(r.y)
        : "f"(s), "f"(x.x), "f"(x.y), "f"(y.x), "f"(y.y));
    return r;
}

__device__ __forceinline__ float2 cmul(float2 a, float2 b) {
    return make_float2(a.x * b.x - a.y * b.y, a.x * b.y + a.y * b.x);
}
__device__ __forceinline__ float2 cadd(float2 a, float2 b) { return f2add(a, b); }
__device__ __forceinline__ float2 csub(float2 a, float2 b) { return f2fma(-1.f, b, a); }  // exact a-b
__device__ __forceinline__ float2 mul_mi(float2 z) { return make_float2(z.y, -z.x); }  // -i*z

// Branchless feature triple from (re, im)
__device__ __forceinline__ void features(float re, float im,
                                         float& lm, float& sv, float& cv) {
    float r2 = fmaxf(re * re + im * im, 1e-45f);
    float inv = rsqrtf(r2);
    lm = __logf(fmaf(r2, inv, 1e-9f));
    sv = im * inv;
    cv = re * inv;
}

// ---------------------------------------------------------------------------
// Fused kernel (R14 math, 6 blocks/SM): inline reduction (blocks < RBLOCKS) +
// one warp = one frame register FFT. Packed f32x2 only where dataflow stays
// packed (adds/subs + butterfly combines); scalar cmul elsewhere.
// ---------------------------------------------------------------------------
__global__ __launch_bounds__(256, 6) void stft_fused(const float* __restrict__ audio,
                                                     float* __restrict__ out) {
    __shared__ float2 s_win[256];           // (hann[2n], hann[2n+1])
    __shared__ float  s_feat[WPB][3][288];  // per-warp transpose staging (stride 9)
    __shared__ float  s_r1[8], s_r2[8];
    __shared__ double s_d1[8], s_d2[8];

    const int tid  = threadIdx.x;
    const int warp = tid >> 5;
    const int p    = tid & 31;
    const unsigned FULL = 0xffffffffu;

    {
        float c0 = cospif((float)(2 * tid)     * (1.f / 256.f));
        float c1 = cospif((float)(2 * tid + 1) * (1.f / 256.f));
        s_win[tid] = make_float2(0.5f * (1.f - c0), 0.5f * (1.f - c1));
    }
    __syncthreads();

    // ---------------- phase A: inline reduction (first RBLOCKS blocks) ---
    if (blockIdx.x < RBLOCKS) {
        const float4* x4 = (const float4*)audio;
        const int gt = blockIdx.x * 256 + tid;          // 0..131071
        float sum = 0.f, sq = 0.f;
        #pragma unroll
        for (int k = 0; k < 8; ++k) {
            float4 v = x4[gt + k * 131072];
            sum += (v.x + v.y) + (v.z + v.w);
            sq  += (v.x*v.x + v.y*v.y) + (v.z*v.z + v.w*v.w);
        }
        #pragma unroll
        for (int o = 16; o > 0; o >>= 1) {
            sum += __shfl_xor_sync(FULL, sum, o);
            sq  += __shfl_xor_sync(FULL, sq,  o);
        }
        if (p == 0) { s_r1[warp] = sum; s_r2[warp] = sq; }
        __syncthreads();
        __shared__ bool is_last;
        if (tid == 0) {
            float a = 0.f, b = 0.f;
            #pragma unroll
            for (int w = 0; w < 8; ++w) { a += s_r1[w]; b += s_r2[w]; }
            g_partial[blockIdx.x] = make_float2(a, b);
            __threadfence();
            is_last = (atomicInc(&g_ctr, RBLOCKS - 1) == RBLOCKS - 1);
        }
        __syncthreads();
        if (is_last) {
            double ds = 0.0, dq = 0.0;
            #pragma unroll
            for (int k = 0; k < 2; ++k) {
                float2 pp = g_partial[tid + 256 * k];
                ds += (double)pp.x; dq += (double)pp.y;
            }
            #pragma unroll
            for (int o = 16; o > 0; o >>= 1) {
                ds += __shfl_xor_sync(FULL, ds, o);
                dq += __shfl_xor_sync(FULL, dq, o);
            }
            if (p == 0) { s_d1[warp] = ds; s_d2[warp] = dq; }
            __syncthreads();
            if (tid == 0) {
                double S = 0.0, SS = 0.0;
                #pragma unroll
                for (int w = 0; w < 8; ++w) { S += s_d1[w]; SS += s_d2[w]; }
                double mean = S / (double)NSAMP;
                double var  = (SS - S * S / (double)NSAMP) / (double)(NSAMP - 1);
                g_c = (float)(mean / sqrt(var));
                __threadfence();
                atomicExch(&g_flag, 1u);
            }
        }
    }

    // ---------------- phase B: per-warp frame FFT -----------------------
    const int frame = blockIdx.x * WPB + warp;
    if (frame >= NFRAMES) return;

    const int base = frame * HOP - NFFT / 2;

    // load + reflect + window + pack (NO -c: folded into bins 0,1 later)
    float2 C[8];
    if (base >= 0 && base + NFFT <= NSAMP) {       // uniform per-warp branch
        #pragma unroll
        for (int q = 0; q < 8; ++q) {
            int n = 32 * q + p;
            float2 v = *(const float2*)(audio + base + 2 * n);
            float2 h = s_win[n];                   // lane-contiguous: conflict-free
            C[q] = make_float2(v.x * h.x, v.y * h.y);
        }
    } else {                                       // frames 0,1,32767,32768 only
        #pragma unroll
        for (int q = 0; q < 8; ++q) {
            int n = 32 * q + p;
            int p0 = base + 2 * n, p1 = p0 + 1;
            if (p0 < 0) p0 = -p0; else if (p0 >= NSAMP) p0 = 2 * NSAMP - 2 - p0;
            if (p1 < 0) p1 = -p1; else if (p1 >= NSAMP) p1 = 2 * NSAMP - 2 - p1;
            float2 h = s_win[n];
            C[q] = make_float2(audio[p0] * h.x, audio[p1] * h.y);
        }
    }

    // step 1: in-register 8-pt DFT over q (adds/subs packed f32x2)
    float2 A[8];
    {
        const float RC = 0.70710678118654752440f;
        float2 t0 = cadd(C[0], C[4]);
        float2 t1 = csub(C[0], C[4]);
        float2 t2 = cadd(C[2], C[6]);
        float2 t3 = csub(C[2], C[6]);
        float2 E0 = cadd(t0, t2);
        float2 E2 = csub(t0, t2);
        float2 t3m = mul_mi(t3);
        float2 E1 = cadd(t1, t3m);
        float2 E3 = csub(t1, t3m);
        float2 u0 = cadd(C[1], C[5]);
        float2 u1 = csub(C[1], C[5]);
        float2 u2 = cadd(C[3], C[7]);
        float2 u3 = csub(C[3], C[7]);
        float2 O0 = cadd(u0, u2);
        float2 O2 = csub(u0, u2);
        float2 u3m = mul_mi(u3);
        float2 O1 = cadd(u1, u3m);
        float2 O3 = csub(u1, u3m);
        float2 w1O1 = cmul(make_float2(RC, -RC), O1);
        float2 w2O2 = mul_mi(O2);
        float2 w3O3 = cmul(make_float2(-RC, -RC), O3);
        A[0] = cadd(E0, O0);   A[4] = csub(E0, O0);
        A[1] = cadd(E1, w1O1); A[5] = csub(E1, w1O1);
        A[2] = cadd(E2, w2O2); A[6] = csub(E2, w2O2);
        A[3] = cadd(E3, w3O3); A[7] = csub(E3, w3O3);
    }

    // step 2: twiddle by e^{-2pi i p s/256} = w1^s (log-depth tree)
    {
        float sn, cs;
        sincospif((float)p * (1.f / 128.f), &sn, &cs);
        float2 w1 = make_float2(cs, -sn);
        float2 w2 = cmul(w1, w1);
        float2 w3 = cmul(w2, w1);
        float2 w4 = cmul(w2, w2);
        float2 w5 = cmul(w4, w1);
        float2 w6 = cmul(w3, w3);
        float2 w7 = cmul(w4, w3);
        C[0] = A[0];
        C[1] = cmul(A[1], w1);
        C[2] = cmul(A[2], w2);
        C[3] = cmul(A[3], w3);
        C[4] = cmul(A[4], w4);
        C[5] = cmul(A[5], w5);
        C[6] = cmul(A[6], w6);
        C[7] = cmul(A[7], w7);
    }

    // step 3: 32-pt DIF across lanes (butterfly combines packed f32x2)
    {
        float sn, cs;
        sincospif((float)(p & 15) * (1.f / 16.f), &sn, &cs);
        float2 w = make_float2(cs, -sn);       // e^{-i*pi*(p&15)/16}, m=16
        #pragma unroll
        for (int st = 0; st < 3; ++st) {
            const int m = 16 >> st;            // 16, 8, 4
            const bool up = (p & m) != 0;
            const float sgn = up ? -1.f : 1.f;
            const float2 we = up ? w : make_float2(1.f, 0.f);
            #pragma unroll
            for (int s = 0; s < 8; ++s) {
                float2 x = C[s];
                float2 y;
                y.x = __shfl_xor_sync(FULL, x.x, m);
                y.y = __shfl_xor_sync(FULL, x.y, m);
                C[s] = cmul(we, f2fma(sgn, x, y));  // we=(1,0) exact identity
            }
            if (st < 2) {
                float2 w2 = cmul(w, w);        // w_{m/2} = (-1)^b w_m^2 (exact)
                if (p & (m >> 1)) { w2.x = -w2.x; w2.y = -w2.y; }
                w = w2;
            }
        }
        // stage m = 2: rotate by -i only on lanes with (p&3)==3 (exact)
        {
            const bool rot = (p & 3) == 3;
            const float sgn = (p & 2) ? -1.f : 1.f;
            #pragma unroll
            for (int s = 0; s < 8; ++s) {
                float2 x = C[s];
                float2 y;
                y.x = __shfl_xor_sync(FULL, x.x, 2);
                y.y = __shfl_xor_sync(FULL, x.y, 2);
                float2 r = f2fma(sgn, x, y);
                C[s] = rot ? mul_mi(r) : r;
            }
        }
        // stage m = 1: twiddle-free butterfly
        {
            const float sgn = (p & 1) ? -1.f : 1.f;
            #pragma unroll
            for (int s = 0; s < 8; ++s) {
                float2 x = C[s];
                float2 y;
                y.x = __shfl_xor_sync(FULL, x.x, 1);
                y.y = __shfl_xor_sync(FULL, x.y, 1);
                C[s] = f2fma(sgn, x, y);
            }
        }
    }
    const int t = __brev(p) >> 27;             // lane p holds Z[s + 8t]

    // ---------------- acquire c (flag long since set) -------------------
    float cbr = 0.f;
    if (p == 0) {
        while (atomicAdd(&g_flag, 0u) == 0u) {}
        __threadfence();
        cbr = *(volatile float*)&g_c;
    }
    cbr = __shfl_sync(FULL, cbr, 0);

    // ---------------- epilogue: real unpack + features ------------------
    float2 wt;
    {
        float sn, cs;
        sincospif((float)t * (1.f / 32.f), &sn, &cs);
        wt = make_float2(cs, -sn);
    }
    const float WS_C[8] = {1.f, 0.999924702f, 0.999698819f, 0.999322385f,
                           0.998795456f, 0.998118113f, 0.997290457f, 0.996312612f};
    const float WS_S[8] = {0.f, 0.012271538f, 0.024541229f, 0.036807223f,
                           0.049067674f, 0.061320736f, 0.073564564f, 0.085797312f};

    float* fr0 = s_feat[warp][0];
    float* fr1 = s_feat[warp][1];
    float* fr2 = s_feat[warp][2];
    const int psrc0 = __brev((32 - t) & 31) >> 27;

    #pragma unroll
    for (int s = 0; s < 8; ++s) {
        float2 zc;
        if (s == 0) {
            zc.x = __shfl_sync(FULL, C[0].x, psrc0);      // Z[(256-8t)%256]
            zc.y = __shfl_sync(FULL, C[0].y, psrc0);
        } else {
            zc.x = __shfl_xor_sync(FULL, C[8 - s].x, 31); // Z[(8-s)+8(31-t)]
            zc.y = __shfl_xor_sync(FULL, C[8 - s].y, 31);
        }
        float2 zk = C[s];
        float xer = 0.5f * (zk.x + zc.x);
        float xei = 0.5f * (zk.y - zc.y);
        float xox = 0.5f * (zk.y + zc.y);
        float xoy = -0.5f * (zk.x - zc.x);
        float2 w = cmul(make_float2(WS_C[s], -WS_S[s]), wt);
        float re = xer + w.x * xox - w.y * xoy;
        float im = xei + w.x * xoy + w.y * xox;
        // c-correction via DFT linearity: H[0]=256, H[1]=-128 (exact)
        if (p == 0) {
            if (s == 0) re -= 256.f * cbr;
            else if (s == 1) re += 128.f * cbr;
        }
        float lm, sv, cv;
        features(re, im, lm, sv, cv);
        int idx = 9 * t + s;                   // conflict-free (9 coprime 32)
        fr0[idx] = lm; fr1[idx] = sv; fr2[idx] = cv;
    }

    float* orow = out + (size_t)frame * OUT_STRIDE;
    if (p == 0) {
        // bin 256: X = Re(Z0) - Im(Z0); H[256]=0 -> no c-correction
        float2 z0 = C[0];
        float re = z0.x - z0.y;
        float lm, sv, cv;
        features(re, 0.f, lm, sv, cv);
        sv = 0.f;
        orow[256] = lm; orow[NBINS + 256] = sv; orow[2 * NBINS + 256] = cv;
    }
    __syncwarp();

    // coalesced copy shared -> gmem
    #pragma unroll
    for (int f = 0; f < 3; ++f) {
        const float* src = s_feat[warp][f];
        #pragma unroll
        for (int cb = 0; cb < 8; ++cb) {
            int k = cb * 32 + p;
            orow[f * NBINS + k] = src[9 * (k >> 3) + (k & 7)];
        }
    }
}

// ---------------------------------------------------------------------------
extern "C" void kernel_launch(void* const* d_in, const int* in_sizes, int n_in,
                              void* d_out, int out_size) {
    const float* audio = (const float*)d_in[0];
    float* out = (float*)d_out;
    stft_fused<<<(NFRAMES + WPB - 1) / WPB, 256>>>(audio, out);
}